// round 6
// baseline (speedup 1.0000x reference)
#include <cuda_runtime.h>
#include <cstdint>

#define BB 2048
#define TT 512
#define DD 178
#define HH 5
#define NG 20
#define SUBROWS 128
#define SUBT 8
#define THR1 256
#define SUB_BYTES (SUBROWS * DD * 4)   // 91136 B

typedef unsigned long long ull;

// [b][t][j][i,f,g,o]; bias folded in; i,f,o pre-scaled by 0.5 (tanh-sigmoid)
__device__ float g_xg[(size_t)BB * TT * NG];

#define SM_MBAR 0
#define SM_W    128                      // 178 * 96 B = 17088
#define SM_XB0  17280
#define SM_XB1  (17280 + SUB_BYTES)
#define SM_TOT  (SM_XB1 + SUB_BYTES)     // 199552

__device__ __forceinline__ ull pack2(float lo, float hi) {
    ull r; asm("mov.b64 %0, {%1,%2};" : "=l"(r) : "f"(lo), "f"(hi)); return r;
}
__device__ __forceinline__ ull dup2(float v) {
    ull r; asm("mov.b64 %0, {%1,%1};" : "=l"(r) : "f"(v)); return r;
}
__device__ __forceinline__ void unpack2(ull v, float& lo, float& hi) {
    asm("mov.b64 {%0,%1}, %2;" : "=f"(lo), "=f"(hi) : "l"(v));
}
__device__ __forceinline__ void fma2(ull& d, ull a, ull b) {
    asm("fma.rn.f32x2 %0, %1, %2, %0;" : "+l"(d) : "l"(a), "l"(b));
}
__device__ __forceinline__ float tanhap(float xv) {
    float r; asm("tanh.approx.f32 %0, %1;" : "=f"(r) : "f"(xv)); return r;
}
__device__ __forceinline__ void mbar_wait(uint32_t mbar, uint32_t parity) {
    asm volatile(
        "{\n\t.reg .pred P;\nW%=:\n\t"
        "mbarrier.try_wait.parity.acquire.cta.shared::cta.b64 P, [%0], %1, 0x989680;\n\t"
        "@P bra D%=;\n\tbra W%=;\nD%=:\n\t}"
        :: "r"(mbar), "r"(parity) : "memory");
}

// ---------------------------------------------------------------------------
// Phase 1: xg = x @ w_ih.T + bias (scaled). 256 threads: 1 row x class-pair.
// gh0 -> (i,f) both x0.5 ; gh1 -> (g x1, o x0.5). TMA-streamed x, 2 buffers.
// ---------------------------------------------------------------------------
extern "C" __global__ void __launch_bounds__(THR1, 1)
gate_gemm(const float* __restrict__ x, const float* __restrict__ w_ih,
          const float* __restrict__ b_ih, const float* __restrict__ b_hh) {
    extern __shared__ char smem[];
    ull* wsu = (ull*)(smem + SM_W);      // [k][12 ull]: gh0 slots 0-4, gh1 slots 6-10
    const uint32_t smb = (uint32_t)__cvta_generic_to_shared(smem);
    const uint32_t mbar0 = smb + SM_MBAR, mbar1 = mbar0 + 8;
    const int tid = threadIdx.x;
    const int r = tid & 127, gh = tid >> 7;
    const size_t row0 = (size_t)blockIdx.x * (SUBROWS * SUBT);

    for (int idx = tid; idx < DD * 10; idx += THR1) {
        int k = idx / 10, q = idx % 10, g2 = q / 5, j = q % 5;
        float slo = (g2 == 0) ? 0.5f : 1.0f;   // i : g
        float shi = 0.5f;                      // f : o
        wsu[k * 12 + g2 * 6 + j] =
            pack2(slo * w_ih[(g2 * 10 + j) * DD + k],
                  shi * w_ih[(g2 * 10 + 5 + j) * DD + k]);
    }
    ull bias[5];
#pragma unroll
    for (int j = 0; j < 5; ++j) {
        int c0 = gh * 10 + j, c1 = gh * 10 + 5 + j;
        float slo = (gh == 0) ? 0.5f : 1.0f;
        bias[j] = pack2(slo * (b_ih[c0] + b_hh[c0]), 0.5f * (b_ih[c1] + b_hh[c1]));
    }
    if (tid == 0) {
        asm volatile("mbarrier.init.shared.b64 [%0], 1;" :: "r"(mbar0));
        asm volatile("mbarrier.init.shared.b64 [%0], 1;" :: "r"(mbar1));
        asm volatile("fence.proxy.async.shared::cta;" ::: "memory");
    }
    __syncthreads();

    auto issue = [&](int s) {
        uint32_t mb  = (s & 1) ? mbar1 : mbar0;
        uint32_t dst = smb + ((s & 1) ? SM_XB1 : SM_XB0);
        const char* src = (const char*)(x + (row0 + (size_t)s * SUBROWS) * DD);
        asm volatile("mbarrier.arrive.expect_tx.shared.b64 _, [%0], %1;"
                     :: "r"(mb), "r"((uint32_t)SUB_BYTES));
        asm volatile(
            "cp.async.bulk.shared::cluster.global.mbarrier::complete_tx::bytes "
            "[%0], [%1], %2, [%3];"
            :: "r"(dst), "l"(src), "r"((uint32_t)SUB_BYTES), "r"(mb) : "memory");
    };
    if (tid == 0) { issue(0); issue(1); }

    const ull* wg = wsu + gh * 6;

    for (int s = 0; s < SUBT; ++s) {
        mbar_wait((s & 1) ? mbar1 : mbar0, (uint32_t)((s >> 1) & 1));
        const float* xr = (const float*)(smem + ((s & 1) ? SM_XB1 : SM_XB0)) + r * DD;

        ull a0 = bias[0], a1 = bias[1], a2 = bias[2], a3 = bias[3], a4 = bias[4];

#pragma unroll 2
        for (int kp = 0; kp < 89; ++kp) {
            float2 x2 = *(const float2*)(xr + 2 * kp);
#pragma unroll
            for (int half = 0; half < 2; ++half) {
                const ull* wp = wg + (2 * kp + half) * 12;
                ulonglong2 q01 = *(const ulonglong2*)(wp);
                ulonglong2 q23 = *(const ulonglong2*)(wp + 2);
                ull q4 = wp[4];
                ull xd = dup2(half ? x2.y : x2.x);
                fma2(a0, xd, q01.x); fma2(a1, xd, q01.y);
                fma2(a2, xd, q23.x); fma2(a3, xd, q23.y);
                fma2(a4, xd, q4);
            }
        }
        __syncthreads();
        if (tid == 0 && s + 2 < SUBT) issue(s + 2);

        size_t row = row0 + (size_t)s * SUBROWS + r;
        char* base = (char*)(g_xg + row * NG) + gh * 8;
        *(ull*)(base)      = a0;
        *(ull*)(base + 16) = a1;
        *(ull*)(base + 32) = a2;
        *(ull*)(base + 48) = a3;
        *(ull*)(base + 64) = a4;
    }
}

// ---------------------------------------------------------------------------
// Phase 2: recurrence, 5 lanes/seq, 4 seqs/warp, 8-deep prefetch ring.
// Activations via MUFU tanh.approx; sigmoid scales pre-folded.
// ---------------------------------------------------------------------------
extern "C" __global__ void __launch_bounds__(128)
lstm_rec(const float* __restrict__ w_hh, const float* __restrict__ w_fc,
         const float* __restrict__ b_fc, float* __restrict__ out) {
    const int lane = threadIdx.x & 31;
    const int warp = threadIdx.x >> 5;
    const int s    = lane >> 3;
    const int j0   = lane & 7;
    const int j    = (j0 < HH) ? j0 : 0;
    const int seq  = (blockIdx.x * 4 + warp) * 4 + s;

    ull wif[HH], wgo[HH];
#pragma unroll
    for (int m = 0; m < HH; ++m) {
        wif[m] = pack2(0.5f * w_hh[j * HH + m], 0.5f * w_hh[(HH + j) * HH + m]);
        wgo[m] = pack2(w_hh[(2 * HH + j) * HH + m], 0.5f * w_hh[(3 * HH + j) * HH + m]);
    }

    const float4* gp4 = (const float4*)g_xg + (size_t)seq * TT * 5 + j;

    float4 rb[8];
#pragma unroll
    for (int p = 0; p < 8; ++p) rb[p] = gp4[p * 5];

    float c = 0.0f, h = 0.0f;
    ull hv2[HH];
#pragma unroll
    for (int m = 0; m < HH; ++m) hv2[m] = 0ULL;

    for (int t0 = 0; t0 < TT; t0 += 8) {
#pragma unroll
        for (int p = 0; p < 8; ++p) {
            float4 cur = rb[p];
            int tn = t0 + p + 8;
            if (tn < TT) rb[p] = gp4[(size_t)tn * 5];

            ull pif = pack2(cur.x, cur.y);   // 0.5*(i,f) pre-act, bias folded
            ull pgo = pack2(cur.z, cur.w);   // (g, 0.5*o)
#pragma unroll
            for (int m = 0; m < HH; ++m) {
                fma2(pif, hv2[m], wif[m]);
                fma2(pgo, hv2[m], wgo[m]);
            }
            float pi, pf, pg, po;
            unpack2(pif, pi, pf);
            unpack2(pgo, pg, po);
            float gi = fmaf(tanhap(pi), 0.5f, 0.5f);   // sigmoid(i)
            float gf = fmaf(tanhap(pf), 0.5f, 0.5f);   // sigmoid(f)
            float gg = tanhap(pg);
            float go = fmaf(tanhap(po), 0.5f, 0.5f);   // sigmoid(o)
            c = fmaf(gf, c, gi * gg);
            h = go * tanhap(c);
            const int base = lane & ~7;
#pragma unroll
            for (int m = 0; m < HH; ++m)
                hv2[m] = dup2(__shfl_sync(0xffffffffu, h, base + m));
        }
    }

    if (j0 < HH) {
        float acc = b_fc[j];
#pragma unroll
        for (int m = 0; m < HH; ++m) {
            float lo, hi;
            unpack2(hv2[m], lo, hi);
            acc = fmaf(fmaxf(lo, 0.0f), w_fc[j * HH + m], acc);
        }
        out[(size_t)seq * HH + j] = acc;
    }
}

extern "C" void kernel_launch(void* const* d_in, const int* in_sizes, int n_in,
                              void* d_out, int out_size) {
    const float* x    = (const float*)d_in[0];
    const float* w_ih = (const float*)d_in[1];
    const float* w_hh = (const float*)d_in[2];
    const float* b_ih = (const float*)d_in[3];
    const float* b_hh = (const float*)d_in[4];
    const float* w_fc = (const float*)d_in[5];
    const float* b_fc = (const float*)d_in[6];

    cudaFuncSetAttribute(gate_gemm, cudaFuncAttributeMaxDynamicSharedMemorySize, SM_TOT);
    gate_gemm<<<(BB * TT) / (SUBROWS * SUBT), THR1, SM_TOT>>>(x, w_ih, b_ih, b_hh);
    lstm_rec<<<BB / 16, 128>>>(w_hh, w_fc, b_fc, (float*)d_out);
}

// round 8
// speedup vs baseline: 1.8037x; 1.8037x over previous
#include <cuda_runtime.h>
#include <cstdint>

#define BB 2048
#define TT 512
#define DD 178
#define HH 5
#define NG 20
#define THR 256
#define CHUNK_ROWS 128
#define CHUNKS 8                      // per CTA: 1024 rows
#define CHUNK_BYTES (CHUNK_ROWS * DD * 4)   // 91136

typedef unsigned long long ull;

// [b][t][j][i,f,g,o]; bias folded; i,f,o pre-scaled by 0.5 (tanh-sigmoid trick)
__device__ float g_xg[(size_t)BB * TT * NG];

// smem byte offsets
#define SO_TMA0 0
#define SO_TMA1 8
#define SO_BF   16                     // B fragments: 12kt*3nt*2p*32lane*8B = 18432
#define SO_S0   19456                  // fp32 staging, 1024-aligned
#define SO_S1   (19456 + CHUNK_BYTES)  // 110592
#define SM_TOT  (SO_S1 + CHUNK_BYTES)  // 201728

__device__ __forceinline__ uint32_t bf2(float hi, float lo) {  // upper=bf(hi), lower=bf(lo)
    uint32_t r; asm("cvt.rn.bf16x2.f32 %0, %1, %2;" : "=r"(r) : "f"(hi), "f"(lo)); return r;
}
__device__ __forceinline__ void cvt_hl(float vx, float vy, uint32_t& h, uint32_t& l) {
    h = bf2(vy, vx);
    float hx = __uint_as_float(h << 16);
    float hy = __uint_as_float(h & 0xffff0000u);
    l = bf2(vy - hy, vx - hx);
}
__device__ __forceinline__ void mma16816(float& d0, float& d1, float& d2, float& d3,
                                         uint32_t a0, uint32_t a1, uint32_t a2, uint32_t a3,
                                         uint32_t b0, uint32_t b1) {
    asm volatile("mma.sync.aligned.m16n8k16.row.col.f32.bf16.bf16.f32 "
                 "{%0,%1,%2,%3}, {%4,%5,%6,%7}, {%8,%9}, {%0,%1,%2,%3};"
                 : "+f"(d0), "+f"(d1), "+f"(d2), "+f"(d3)
                 : "r"(a0), "r"(a1), "r"(a2), "r"(a3), "r"(b0), "r"(b1));
}
__device__ __forceinline__ float tanhap(float xv) {
    float r; asm("tanh.approx.f32 %0, %1;" : "=f"(r) : "f"(xv)); return r;
}
__device__ __forceinline__ void mbar_wait(uint32_t mbar, uint32_t parity) {
    asm volatile(
        "{\n\t.reg .pred P;\nW%=:\n\t"
        "mbarrier.try_wait.parity.acquire.cta.shared::cta.b64 P, [%0], %1, 0x989680;\n\t"
        "@P bra D%=;\n\tbra W%=;\nD%=:\n\t}"
        :: "r"(mbar), "r"(parity) : "memory");
}

// ---------------------------------------------------------------------------
// Phase 1: xg = x @ w_ih.T + scaled bias, via mma.sync bf16 hi/lo (3 passes).
// M = 1M rows (1024 CTAs x 1024), N = 20 (pad 24 = 3 n8 tiles), K = 178 (pad 192).
// ---------------------------------------------------------------------------
extern "C" __global__ void __launch_bounds__(THR, 1)
gate_mma(const float* __restrict__ x, const float* __restrict__ w_ih,
         const float* __restrict__ b_ih, const float* __restrict__ b_hh) {
    extern __shared__ char smem[];
    const uint32_t smb = (uint32_t)__cvta_generic_to_shared(smem);
    const int tid = threadIdx.x;
    const int warp = tid >> 5, lane = tid & 31;
    const int g = lane >> 2, t = lane & 3;
    const size_t row_base = (size_t)blockIdx.x * (CHUNK_ROWS * CHUNKS);

    uint2* bfrag = (uint2*)(smem + SO_BF);

    // --- pack B (weights) into fragment-ordered smem, hi/lo split ---
    // col n = j*4 + c  (c: 0=i,1=f,2=g,3=o ; w_ih row = c*5+j ; scale 0.5 except g)
    for (int idx = tid; idx < 12 * 3 * 32; idx += THR) {
        int l = idx & 31, nt = (idx >> 5) % 3, kt = idx / 96;
        int n = nt * 8 + (l >> 2);
        int k = kt * 16 + 2 * (l & 3);
        float w0 = 0, w1 = 0, w2 = 0, w3 = 0;
        if (n < NG) {
            int c = n & 3, j = n >> 2;
            float s = (c == 2) ? 1.0f : 0.5f;
            const float* wr = w_ih + (c * 5 + j) * DD;
            if (k     < DD) w0 = s * wr[k];
            if (k + 1 < DD) w1 = s * wr[k + 1];
            if (k + 8 < DD) w2 = s * wr[k + 8];
            if (k + 9 < DD) w3 = s * wr[k + 9];
        }
        uint32_t b0h, b0l, b1h, b1l;
        cvt_hl(w0, w1, b0h, b0l);
        cvt_hl(w2, w3, b1h, b1l);
        bfrag[(((kt * 3 + nt) * 2 + 0) * 32) + l] = make_uint2(b0h, b1h);
        bfrag[(((kt * 3 + nt) * 2 + 1) * 32) + l] = make_uint2(b0l, b1l);
    }

    // --- per-thread scaled biases for accumulator init ---
    float bias0[3], bias1[3];
#pragma unroll
    for (int nt = 0; nt < 3; ++nt) {
        int n0 = nt * 8 + 2 * t;
        bias0[nt] = bias1[nt] = 0.0f;
        if (n0 < NG) {
            int c = n0 & 3, j = n0 >> 2;
            float s = (c == 2) ? 1.0f : 0.5f;
            bias0[nt] = s * (b_ih[c * 5 + j] + b_hh[c * 5 + j]);
            c = (n0 + 1) & 3; j = (n0 + 1) >> 2;
            s = (c == 2) ? 1.0f : 0.5f;
            bias1[nt] = s * (b_ih[c * 5 + j] + b_hh[c * 5 + j]);
        }
    }

    if (tid == 0) {
        asm volatile("mbarrier.init.shared.b64 [%0], 1;" :: "r"(smb + SO_TMA0));
        asm volatile("mbarrier.init.shared.b64 [%0], 1;" :: "r"(smb + SO_TMA1));
        asm volatile("fence.proxy.async.shared::cta;" ::: "memory");
    }
    __syncthreads();

    auto issue = [&](int ch) {
        uint32_t mb  = smb + ((ch & 1) ? SO_TMA1 : SO_TMA0);
        uint32_t dst = smb + ((ch & 1) ? SO_S1 : SO_S0);
        const char* src = (const char*)(x + (row_base + (size_t)ch * CHUNK_ROWS) * DD);
        asm volatile("mbarrier.arrive.expect_tx.shared.b64 _, [%0], %1;"
                     :: "r"(mb), "r"((uint32_t)CHUNK_BYTES));
        asm volatile(
            "cp.async.bulk.shared::cluster.global.mbarrier::complete_tx::bytes "
            "[%0], [%1], %2, [%3];"
            :: "r"(dst), "l"(src), "r"((uint32_t)CHUNK_BYTES), "r"(mb) : "memory");
    };
    if (tid == 0) { issue(0); issue(1); }

    for (int ch = 0; ch < CHUNKS; ++ch) {
        mbar_wait(smb + ((ch & 1) ? SO_TMA1 : SO_TMA0), (uint32_t)((ch >> 1) & 1));
        const float* stage = (const float*)(smem + ((ch & 1) ? SO_S1 : SO_S0));
        const float* pr = stage + (warp * 16 + g) * DD;   // row g of this warp's stripe

        float d[3][4];
#pragma unroll
        for (int nt = 0; nt < 3; ++nt) {
            d[nt][0] = bias0[nt]; d[nt][1] = bias1[nt];
            d[nt][2] = bias0[nt]; d[nt][3] = bias1[nt];
        }

#pragma unroll
        for (int kt = 0; kt < 12; ++kt) {
            int k0 = kt * 16 + 2 * t;
            bool v0 = (k0 <= DD - 2);
            bool v2 = (k0 + 8 <= DD - 2);
            float2 z = make_float2(0.0f, 0.0f);
            float2 A0 = v0 ? *(const float2*)(pr + k0)            : z;
            float2 A1 = v0 ? *(const float2*)(pr + 8 * DD + k0)   : z;
            float2 A2 = v2 ? *(const float2*)(pr + k0 + 8)        : z;
            float2 A3 = v2 ? *(const float2*)(pr + 8 * DD + k0 + 8) : z;
            uint32_t ah0, al0, ah1, al1, ah2, al2, ah3, al3;
            cvt_hl(A0.x, A0.y, ah0, al0);
            cvt_hl(A1.x, A1.y, ah1, al1);
            cvt_hl(A2.x, A2.y, ah2, al2);
            cvt_hl(A3.x, A3.y, ah3, al3);
#pragma unroll
            for (int nt = 0; nt < 3; ++nt) {
                uint2 BH = bfrag[(((kt * 3 + nt) * 2 + 0) * 32) + lane];
                uint2 BL = bfrag[(((kt * 3 + nt) * 2 + 1) * 32) + lane];
                mma16816(d[nt][0], d[nt][1], d[nt][2], d[nt][3],
                         ah0, ah1, ah2, ah3, BH.x, BH.y);
                mma16816(d[nt][0], d[nt][1], d[nt][2], d[nt][3],
                         ah0, ah1, ah2, ah3, BL.x, BL.y);
                mma16816(d[nt][0], d[nt][1], d[nt][2], d[nt][3],
                         al0, al1, al2, al3, BH.x, BH.y);
            }
        }
        __syncthreads();                 // all staging reads done
        if (tid == 0 && ch + 2 < CHUNKS) issue(ch + 2);

        // epilogue: D cols (n0, n0+1) are exactly an 8B chunk of the record
        size_t row = row_base + (size_t)ch * CHUNK_ROWS + warp * 16 + g;
#pragma unroll
        for (int nt = 0; nt < 3; ++nt) {
            int n0 = nt * 8 + 2 * t;
            if (n0 < NG) {
                *(float2*)(g_xg + row * NG + n0)       = make_float2(d[nt][0], d[nt][1]);
                *(float2*)(g_xg + (row + 8) * NG + n0) = make_float2(d[nt][2], d[nt][3]);
            }
        }
    }
}

// ---------------------------------------------------------------------------
// Phase 2: recurrence, 5 lanes/seq, 4 seqs/warp, 8-deep prefetch ring.
// Scalar FFMA gates (f32x2 decomposes on sm_103 anyway); MUFU tanh.approx.
// ---------------------------------------------------------------------------
extern "C" __global__ void __launch_bounds__(128)
lstm_rec(const float* __restrict__ w_hh, const float* __restrict__ w_fc,
         const float* __restrict__ b_fc, float* __restrict__ out) {
    const int lane = threadIdx.x & 31;
    const int warp = threadIdx.x >> 5;
    const int s    = lane >> 3;
    const int j0   = lane & 7;
    const int j    = (j0 < HH) ? j0 : 0;
    const int seq  = (blockIdx.x * 4 + warp) * 4 + s;

    float wi[HH], wf[HH], wg[HH], wo[HH];
#pragma unroll
    for (int m = 0; m < HH; ++m) {
        wi[m] = 0.5f * w_hh[j * HH + m];
        wf[m] = 0.5f * w_hh[(HH + j) * HH + m];
        wg[m] =        w_hh[(2 * HH + j) * HH + m];
        wo[m] = 0.5f * w_hh[(3 * HH + j) * HH + m];
    }

    const float4* gp4 = (const float4*)g_xg + (size_t)seq * TT * 5 + j;

    float4 rb[8];
#pragma unroll
    for (int p = 0; p < 8; ++p) rb[p] = gp4[p * 5];

    float c = 0.0f, h = 0.0f;
    float hv[HH];
#pragma unroll
    for (int m = 0; m < HH; ++m) hv[m] = 0.0f;

    for (int t0 = 0; t0 < TT; t0 += 8) {
#pragma unroll
        for (int p = 0; p < 8; ++p) {
            float4 cur = rb[p];
            int tn = t0 + p + 8;
            if (tn < TT) rb[p] = gp4[(size_t)tn * 5];

            float pi = cur.x, pf = cur.y, pg = cur.z, po = cur.w;
#pragma unroll
            for (int m = 0; m < HH; ++m) {
                pi = fmaf(hv[m], wi[m], pi);
                pf = fmaf(hv[m], wf[m], pf);
                pg = fmaf(hv[m], wg[m], pg);
                po = fmaf(hv[m], wo[m], po);
            }
            float gi = fmaf(tanhap(pi), 0.5f, 0.5f);
            float gf = fmaf(tanhap(pf), 0.5f, 0.5f);
            float gg = tanhap(pg);
            float go = fmaf(tanhap(po), 0.5f, 0.5f);
            c = fmaf(gf, c, gi * gg);
            h = go * tanhap(c);
            const int base = lane & ~7;
#pragma unroll
            for (int m = 0; m < HH; ++m)
                hv[m] = __shfl_sync(0xffffffffu, h, base + m);
        }
    }

    if (j0 < HH) {
        float acc = b_fc[j];
#pragma unroll
        for (int m = 0; m < HH; ++m)
            acc = fmaf(fmaxf(hv[m], 0.0f), w_fc[j * HH + m], acc);
        out[(size_t)seq * HH + j] = acc;
    }
}

extern "C" void kernel_launch(void* const* d_in, const int* in_sizes, int n_in,
                              void* d_out, int out_size) {
    const float* x    = (const float*)d_in[0];
    const float* w_ih = (const float*)d_in[1];
    const float* w_hh = (const float*)d_in[2];
    const float* b_ih = (const float*)d_in[3];
    const float* b_hh = (const float*)d_in[4];
    const float* w_fc = (const float*)d_in[5];
    const float* b_fc = (const float*)d_in[6];

    cudaFuncSetAttribute(gate_mma, cudaFuncAttributeMaxDynamicSharedMemorySize, SM_TOT);
    gate_mma<<<(BB * TT) / (CHUNK_ROWS * CHUNKS), THR, SM_TOT>>>(x, w_ih, b_ih, b_hh);
    lstm_rec<<<BB / 16, 128>>>(w_hh, w_fc, b_fc, (float*)d_out);
}

// round 9
// speedup vs baseline: 2.0164x; 1.1180x over previous
#include <cuda_runtime.h>
#include <cuda_fp16.h>
#include <cstdint>

#define BB 2048
#define TT 512
#define DD 178
#define HH 5
#define NG 20
#define THR 256
#define CHUNK_ROWS 128
#define CHUNKS 8
#define CHUNK_BYTES (CHUNK_ROWS * DD * 4)   // 91136

typedef unsigned long long ull;

// fp16 gate pre-activations [b][t][j][i,f,g,o]; bias folded; i,f,o pre-scaled 0.5
__device__ __half g_xg[(size_t)BB * TT * NG];

#define SO_TMA0 0
#define SO_TMA1 8
#define SO_BF   16
#define SO_S0   19456
#define SO_S1   (19456 + CHUNK_BYTES)
#define SM_TOT  (SO_S1 + CHUNK_BYTES)

__device__ __forceinline__ uint32_t bf2(float hi, float lo) {
    uint32_t r; asm("cvt.rn.bf16x2.f32 %0, %1, %2;" : "=r"(r) : "f"(hi), "f"(lo)); return r;
}
__device__ __forceinline__ uint32_t h2pack(float lo, float hi) {
    uint32_t r; asm("cvt.rn.f16x2.f32 %0, %1, %2;" : "=r"(r) : "f"(hi), "f"(lo)); return r;
}
__device__ __forceinline__ void cvt_hl(float vx, float vy, uint32_t& h, uint32_t& l) {
    h = bf2(vy, vx);
    float hx = __uint_as_float(h << 16);
    float hy = __uint_as_float(h & 0xffff0000u);
    l = bf2(vy - hy, vx - hx);
}
__device__ __forceinline__ void mma16816(float& d0, float& d1, float& d2, float& d3,
                                         uint32_t a0, uint32_t a1, uint32_t a2, uint32_t a3,
                                         uint32_t b0, uint32_t b1) {
    asm volatile("mma.sync.aligned.m16n8k16.row.col.f32.bf16.bf16.f32 "
                 "{%0,%1,%2,%3}, {%4,%5,%6,%7}, {%8,%9}, {%0,%1,%2,%3};"
                 : "+f"(d0), "+f"(d1), "+f"(d2), "+f"(d3)
                 : "r"(a0), "r"(a1), "r"(a2), "r"(a3), "r"(b0), "r"(b1));
}
__device__ __forceinline__ float tanhap(float xv) {
    float r; asm("tanh.approx.f32 %0, %1;" : "=f"(r) : "f"(xv)); return r;
}
__device__ __forceinline__ void mbar_wait(uint32_t mbar, uint32_t parity) {
    asm volatile(
        "{\n\t.reg .pred P;\nW%=:\n\t"
        "mbarrier.try_wait.parity.acquire.cta.shared::cta.b64 P, [%0], %1, 0x989680;\n\t"
        "@P bra D%=;\n\tbra W%=;\nD%=:\n\t}"
        :: "r"(mbar), "r"(parity) : "memory");
}

// ---------------------------------------------------------------------------
// Phase 1: xg = x @ w_ih.T + scaled bias, mma.sync bf16 hi/lo, fp16 output.
// ---------------------------------------------------------------------------
extern "C" __global__ void __launch_bounds__(THR, 1)
gate_mma(const float* __restrict__ x, const float* __restrict__ w_ih,
         const float* __restrict__ b_ih, const float* __restrict__ b_hh) {
    extern __shared__ char smem[];
    const uint32_t smb = (uint32_t)__cvta_generic_to_shared(smem);
    const int tid = threadIdx.x;
    const int warp = tid >> 5, lane = tid & 31;
    const int g = lane >> 2, t = lane & 3;
    const size_t row_base = (size_t)blockIdx.x * (CHUNK_ROWS * CHUNKS);

    uint2* bfrag = (uint2*)(smem + SO_BF);

    for (int idx = tid; idx < 12 * 3 * 32; idx += THR) {
        int l = idx & 31, nt = (idx >> 5) % 3, kt = idx / 96;
        int n = nt * 8 + (l >> 2);
        int k = kt * 16 + 2 * (l & 3);
        float w0 = 0, w1 = 0, w2 = 0, w3 = 0;
        if (n < NG) {
            int c = n & 3, j = n >> 2;
            float s = (c == 2) ? 1.0f : 0.5f;
            const float* wr = w_ih + (c * 5 + j) * DD;
            if (k     < DD) w0 = s * wr[k];
            if (k + 1 < DD) w1 = s * wr[k + 1];
            if (k + 8 < DD) w2 = s * wr[k + 8];
            if (k + 9 < DD) w3 = s * wr[k + 9];
        }
        uint32_t b0h, b0l, b1h, b1l;
        cvt_hl(w0, w1, b0h, b0l);
        cvt_hl(w2, w3, b1h, b1l);
        bfrag[(((kt * 3 + nt) * 2 + 0) * 32) + l] = make_uint2(b0h, b1h);
        bfrag[(((kt * 3 + nt) * 2 + 1) * 32) + l] = make_uint2(b0l, b1l);
    }

    float bias0[3], bias1[3];
#pragma unroll
    for (int nt = 0; nt < 3; ++nt) {
        int n0 = nt * 8 + 2 * t;
        bias0[nt] = bias1[nt] = 0.0f;
        if (n0 < NG) {
            int c = n0 & 3, j = n0 >> 2;
            float s = (c == 2) ? 1.0f : 0.5f;
            bias0[nt] = s * (b_ih[c * 5 + j] + b_hh[c * 5 + j]);
            c = (n0 + 1) & 3; j = (n0 + 1) >> 2;
            s = (c == 2) ? 1.0f : 0.5f;
            bias1[nt] = s * (b_ih[c * 5 + j] + b_hh[c * 5 + j]);
        }
    }

    if (tid == 0) {
        asm volatile("mbarrier.init.shared.b64 [%0], 1;" :: "r"(smb + SO_TMA0));
        asm volatile("mbarrier.init.shared.b64 [%0], 1;" :: "r"(smb + SO_TMA1));
        asm volatile("fence.proxy.async.shared::cta;" ::: "memory");
    }
    __syncthreads();

    ull pol;
    asm("createpolicy.fractional.L2::evict_first.b64 %0, 1.0;" : "=l"(pol));

    auto issue = [&](int ch) {
        uint32_t mb  = smb + ((ch & 1) ? SO_TMA1 : SO_TMA0);
        uint32_t dst = smb + ((ch & 1) ? SO_S1 : SO_S0);
        const char* src = (const char*)(x + (row_base + (size_t)ch * CHUNK_ROWS) * DD);
        asm volatile("mbarrier.arrive.expect_tx.shared.b64 _, [%0], %1;"
                     :: "r"(mb), "r"((uint32_t)CHUNK_BYTES));
        asm volatile(
            "cp.async.bulk.shared::cluster.global.mbarrier::complete_tx::bytes"
            ".L2::cache_hint [%0], [%1], %2, [%3], %4;"
            :: "r"(dst), "l"(src), "r"((uint32_t)CHUNK_BYTES), "r"(mb), "l"(pol)
            : "memory");
    };
    if (tid == 0) { issue(0); issue(1); }

    for (int ch = 0; ch < CHUNKS; ++ch) {
        mbar_wait(smb + ((ch & 1) ? SO_TMA1 : SO_TMA0), (uint32_t)((ch >> 1) & 1));
        const float* stage = (const float*)(smem + ((ch & 1) ? SO_S1 : SO_S0));
        const float* pr = stage + (warp * 16 + g) * DD;

        float d[3][4];
#pragma unroll
        for (int nt = 0; nt < 3; ++nt) {
            d[nt][0] = bias0[nt]; d[nt][1] = bias1[nt];
            d[nt][2] = bias0[nt]; d[nt][3] = bias1[nt];
        }

#pragma unroll
        for (int kt = 0; kt < 12; ++kt) {
            int k0 = kt * 16 + 2 * t;
            bool v0 = (k0 <= DD - 2);
            bool v2 = (k0 + 8 <= DD - 2);
            float2 z = make_float2(0.0f, 0.0f);
            float2 A0 = v0 ? *(const float2*)(pr + k0)              : z;
            float2 A1 = v0 ? *(const float2*)(pr + 8 * DD + k0)     : z;
            float2 A2 = v2 ? *(const float2*)(pr + k0 + 8)          : z;
            float2 A3 = v2 ? *(const float2*)(pr + 8 * DD + k0 + 8) : z;
            uint32_t ah0, al0, ah1, al1, ah2, al2, ah3, al3;
            cvt_hl(A0.x, A0.y, ah0, al0);
            cvt_hl(A1.x, A1.y, ah1, al1);
            cvt_hl(A2.x, A2.y, ah2, al2);
            cvt_hl(A3.x, A3.y, ah3, al3);
#pragma unroll
            for (int nt = 0; nt < 3; ++nt) {
                uint2 BH = bfrag[(((kt * 3 + nt) * 2 + 0) * 32) + lane];
                uint2 BL = bfrag[(((kt * 3 + nt) * 2 + 1) * 32) + lane];
                mma16816(d[nt][0], d[nt][1], d[nt][2], d[nt][3],
                         ah0, ah1, ah2, ah3, BH.x, BH.y);
                mma16816(d[nt][0], d[nt][1], d[nt][2], d[nt][3],
                         ah0, ah1, ah2, ah3, BL.x, BL.y);
                mma16816(d[nt][0], d[nt][1], d[nt][2], d[nt][3],
                         al0, al1, al2, al3, BH.x, BH.y);
            }
        }
        __syncthreads();
        if (tid == 0 && ch + 2 < CHUNKS) issue(ch + 2);

        size_t row = row_base + (size_t)ch * CHUNK_ROWS + warp * 16 + g;
#pragma unroll
        for (int nt = 0; nt < 3; ++nt) {
            int n0 = nt * 8 + 2 * t;
            if (n0 < NG) {
                *(uint32_t*)((char*)g_xg + row * 40 + n0 * 2) =
                    h2pack(d[nt][0], d[nt][1]);
                *(uint32_t*)((char*)g_xg + (row + 8) * 40 + n0 * 2) =
                    h2pack(d[nt][2], d[nt][3]);
            }
        }
    }
}

// ---------------------------------------------------------------------------
// Phase 2: recurrence. 5 lanes/unit-j, 4 groups/warp, 2 sequences per thread
// (independent chains overlap the latency path). 8-deep uint2 prefetch rings.
// ---------------------------------------------------------------------------
extern "C" __global__ void __launch_bounds__(128)
lstm_rec(const float* __restrict__ w_hh, const float* __restrict__ w_fc,
         const float* __restrict__ b_fc, float* __restrict__ out) {
    const int lane = threadIdx.x & 31;
    const int warp = threadIdx.x >> 5;
    const int j0   = lane & 7;
    const int j    = (j0 < HH) ? j0 : 0;
    const int gidx = (blockIdx.x * 4 + warp) * 4 + (lane >> 3);  // 0..1023
    const int seqA = gidx, seqB = gidx + 1024;

    float wi[HH], wf[HH], wg[HH], wo[HH];
#pragma unroll
    for (int m = 0; m < HH; ++m) {
        wi[m] = 0.5f * w_hh[j * HH + m];
        wf[m] = 0.5f * w_hh[(HH + j) * HH + m];
        wg[m] =        w_hh[(2 * HH + j) * HH + m];
        wo[m] = 0.5f * w_hh[(3 * HH + j) * HH + m];
    }

    const uint2* gpA = (const uint2*)((const char*)g_xg + (size_t)seqA * TT * 40) + j;
    const uint2* gpB = (const uint2*)((const char*)g_xg + (size_t)seqB * TT * 40) + j;

    uint2 rA[8], rB[8];
#pragma unroll
    for (int p = 0; p < 8; ++p) { rA[p] = gpA[p * 5]; rB[p] = gpB[p * 5]; }

    float cA = 0.0f, hA = 0.0f, cB = 0.0f, hB = 0.0f;
    float hvA[HH], hvB[HH];
#pragma unroll
    for (int m = 0; m < HH; ++m) { hvA[m] = 0.0f; hvB[m] = 0.0f; }

    const int base = lane & ~7;

    for (int t0 = 0; t0 < TT; t0 += 8) {
#pragma unroll
        for (int p = 0; p < 8; ++p) {
            uint2 curA = rA[p], curB = rB[p];
            int tn = t0 + p + 8;
            if (tn < TT) { rA[p] = gpA[(size_t)tn * 5]; rB[p] = gpB[(size_t)tn * 5]; }

            float2 ifA = __half22float2(*(const __half2*)&curA.x);
            float2 goA = __half22float2(*(const __half2*)&curA.y);
            float2 ifB = __half22float2(*(const __half2*)&curB.x);
            float2 goB = __half22float2(*(const __half2*)&curB.y);

            float piA = ifA.x, pfA = ifA.y, pgA = goA.x, poA = goA.y;
            float piB = ifB.x, pfB = ifB.y, pgB = goB.x, poB = goB.y;
#pragma unroll
            for (int m = 0; m < HH; ++m) {
                piA = fmaf(hvA[m], wi[m], piA);
                pfA = fmaf(hvA[m], wf[m], pfA);
                pgA = fmaf(hvA[m], wg[m], pgA);
                poA = fmaf(hvA[m], wo[m], poA);
                piB = fmaf(hvB[m], wi[m], piB);
                pfB = fmaf(hvB[m], wf[m], pfB);
                pgB = fmaf(hvB[m], wg[m], pgB);
                poB = fmaf(hvB[m], wo[m], poB);
            }
            float giA = fmaf(tanhap(piA), 0.5f, 0.5f);
            float gfA = fmaf(tanhap(pfA), 0.5f, 0.5f);
            float ggA = tanhap(pgA);
            float goAa = fmaf(tanhap(poA), 0.5f, 0.5f);
            float giB = fmaf(tanhap(piB), 0.5f, 0.5f);
            float gfB = fmaf(tanhap(pfB), 0.5f, 0.5f);
            float ggB = tanhap(pgB);
            float goBa = fmaf(tanhap(poB), 0.5f, 0.5f);
            cA = fmaf(gfA, cA, giA * ggA);
            cB = fmaf(gfB, cB, giB * ggB);
            hA = goAa * tanhap(cA);
            hB = goBa * tanhap(cB);
#pragma unroll
            for (int m = 0; m < HH; ++m) {
                hvA[m] = __shfl_sync(0xffffffffu, hA, base + m);
                hvB[m] = __shfl_sync(0xffffffffu, hB, base + m);
            }
        }
    }

    if (j0 < HH) {
        float aA = b_fc[j], aB = b_fc[j];
#pragma unroll
        for (int m = 0; m < HH; ++m) {
            aA = fmaf(fmaxf(hvA[m], 0.0f), w_fc[j * HH + m], aA);
            aB = fmaf(fmaxf(hvB[m], 0.0f), w_fc[j * HH + m], aB);
        }
        out[(size_t)seqA * HH + j] = aA;
        out[(size_t)seqB * HH + j] = aB;
    }
}

extern "C" void kernel_launch(void* const* d_in, const int* in_sizes, int n_in,
                              void* d_out, int out_size) {
    const float* x    = (const float*)d_in[0];
    const float* w_ih = (const float*)d_in[1];
    const float* w_hh = (const float*)d_in[2];
    const float* b_ih = (const float*)d_in[3];
    const float* b_hh = (const float*)d_in[4];
    const float* w_fc = (const float*)d_in[5];
    const float* b_fc = (const float*)d_in[6];

    cudaFuncSetAttribute(gate_mma, cudaFuncAttributeMaxDynamicSharedMemorySize, SM_TOT);
    gate_mma<<<(BB * TT) / (CHUNK_ROWS * CHUNKS), THR, SM_TOT>>>(x, w_ih, b_ih, b_hh);
    lstm_rec<<<64, 128>>>(w_hh, w_fc, b_fc, (float*)d_out);
}